// round 1
// baseline (speedup 1.0000x reference)
#include <cuda_runtime.h>
#include <cstdint>

#define Bc   16
#define Pc   4096
#define Sc   1024
#define Kc   16
#define INF_ 256
#define OUTF 512
#define NTOT (Bc * Pc)   // 65536
#define QTOT (Bc * Sc)   // 16384

// ---- scratch (device globals; no runtime allocation allowed) ----
__device__ float g_h[(size_t)NTOT * OUTF];      // 128 MB: MLP output (pre-BN)
__device__ float g_dist[(size_t)QTOT * Pc];     // 256 MB: knn distances
__device__ int   g_fps[QTOT];                   // local fps indices per cloud
__device__ int   g_knn[QTOT * Kc];              // global neighbor row indices
__device__ float g_sum[OUTF];
__device__ float g_sumsq[OUTF];
__device__ float g_a[OUTF];                     // gamma * rstd
__device__ float g_b2[OUTF];                    // beta - mu * gamma * rstd
__device__ float g_xnorm[NTOT];

// ============================================================
// zero the column-sum accumulators
// ============================================================
__global__ void zero_sums_kernel() {
    int t = threadIdx.x;
    if (t < OUTF) { g_sum[t] = 0.f; g_sumsq[t] = 0.f; }
}

// ============================================================
// FPS: one block per cloud, 256 threads, 16 points/thread.
// Replicates XLA arithmetic exactly: d = (dx*dx + dy*dy) + dz*dz,
// no FMA contraction, argmax first-wins tie-break.
// Also gathers positions / batch outputs at the end.
// ============================================================
__global__ void fps_kernel(const float* __restrict__ pos,
                           float* __restrict__ out_pos,   // may be null
                           float* __restrict__ out_batch, // may be null
                           int write_pos, int write_batch) {
    const int c   = blockIdx.x;
    const int tid = threadIdx.x;
    const int wid = tid >> 5;
    const int lane = tid & 31;
    const float* p = pos + (size_t)c * Pc * 3;

    float px[16], py[16], pz[16], md[16];
#pragma unroll
    for (int j = 0; j < 16; ++j) {
        int i = tid + j * 256;
        px[j] = p[i * 3 + 0];
        py[j] = p[i * 3 + 1];
        pz[j] = p[i * 3 + 2];
        md[j] = 3.402823466e+38f;
    }

    __shared__ float s_val[8];
    __shared__ int   s_idx[8];
    __shared__ int   s_last;

    int last = 0;
    if (tid == 0) g_fps[c * Sc + 0] = 0;

    for (int t = 1; t < Sc; ++t) {
        float lx = p[last * 3 + 0];
        float ly = p[last * 3 + 1];
        float lz = p[last * 3 + 2];

        float bestv = -1.0f;
        int   besti = 0x7fffffff;
#pragma unroll
        for (int j = 0; j < 16; ++j) {
            float dx = __fsub_rn(px[j], lx);
            float dy = __fsub_rn(py[j], ly);
            float dz = __fsub_rn(pz[j], lz);
            float d  = __fadd_rn(__fadd_rn(__fmul_rn(dx, dx), __fmul_rn(dy, dy)),
                                 __fmul_rn(dz, dz));
            md[j] = fminf(md[j], d);
            int idx = tid + j * 256;
            // strict > keeps lowest index on ties within thread (j increasing = idx increasing)
            if (md[j] > bestv || (md[j] == bestv && idx < besti)) { bestv = md[j]; besti = idx; }
        }
        // warp argmax, first(lowest idx)-wins ties
#pragma unroll
        for (int off = 16; off > 0; off >>= 1) {
            float ov = __shfl_xor_sync(0xffffffffu, bestv, off);
            int   oi = __shfl_xor_sync(0xffffffffu, besti, off);
            if (ov > bestv || (ov == bestv && oi < besti)) { bestv = ov; besti = oi; }
        }
        if (lane == 0) { s_val[wid] = bestv; s_idx[wid] = besti; }
        __syncthreads();
        if (wid == 0) {
            float v = (lane < 8) ? s_val[lane] : -1.0f;
            int   i = (lane < 8) ? s_idx[lane] : 0x7fffffff;
#pragma unroll
            for (int off = 4; off > 0; off >>= 1) {
                float ov = __shfl_xor_sync(0xffffffffu, v, off);
                int   oi = __shfl_xor_sync(0xffffffffu, i, off);
                if (ov > v || (ov == v && oi < i)) { v = ov; i = oi; }
            }
            if (lane == 0) { s_last = i; g_fps[c * Sc + t] = i; }
        }
        __syncthreads();
        last = s_last;
    }

    // gather outputs: positions[fps], batch[fps]
    for (int s = tid; s < Sc; s += 256) {
        int li = g_fps[c * Sc + s];
        int q  = c * Sc + s;
        if (write_pos) {
            out_pos[q * 3 + 0] = p[li * 3 + 0];
            out_pos[q * 3 + 1] = p[li * 3 + 1];
            out_pos[q * 3 + 2] = p[li * 3 + 2];
        }
        if (write_batch) out_batch[q] = (float)c;
    }
}

// ============================================================
// MLP GEMM: g_h[65536,512] = features[65536,256] @ W[256,512] + b
// 128x128 tile, BK=16, 256 threads, 8x8 per thread.
// ============================================================
#define BM 128
#define BN 128
#define BK 16
__global__ __launch_bounds__(256) void gemm_mlp_kernel(
    const float* __restrict__ A, const float* __restrict__ W,
    const float* __restrict__ bias) {
    __shared__ float As[BK][BM];
    __shared__ float Bs[BK][BN];
    const int bm = blockIdx.y * BM;
    const int bn = blockIdx.x * BN;
    const int tid = threadIdx.x;
    const int tx = tid & 15, ty = tid >> 4;

    float acc[8][8];
#pragma unroll
    for (int i = 0; i < 8; ++i)
#pragma unroll
        for (int j = 0; j < 8; ++j) acc[i][j] = 0.f;

    for (int k0 = 0; k0 < INF_; k0 += BK) {
#pragma unroll
        for (int it = 0; it < 2; ++it) {
            int f = tid + it * 256;
            int r = f >> 2, kq = (f & 3) * 4;
            float4 v = *(const float4*)(A + (size_t)(bm + r) * INF_ + k0 + kq);
            As[kq + 0][r] = v.x; As[kq + 1][r] = v.y;
            As[kq + 2][r] = v.z; As[kq + 3][r] = v.w;
        }
#pragma unroll
        for (int it = 0; it < 2; ++it) {
            int f = tid + it * 256;
            int r = f >> 5, cq = (f & 31) * 4;
            float4 v = *(const float4*)(W + (size_t)(k0 + r) * OUTF + bn + cq);
            *(float4*)&Bs[r][cq] = v;
        }
        __syncthreads();
#pragma unroll
        for (int kk = 0; kk < BK; ++kk) {
            float ra[8], rb[8];
#pragma unroll
            for (int i = 0; i < 8; ++i) ra[i] = As[kk][ty * 8 + i];
#pragma unroll
            for (int j = 0; j < 8; ++j) rb[j] = Bs[kk][tx * 8 + j];
#pragma unroll
            for (int i = 0; i < 8; ++i)
#pragma unroll
                for (int j = 0; j < 8; ++j) acc[i][j] += ra[i] * rb[j];
        }
        __syncthreads();
    }
#pragma unroll
    for (int i = 0; i < 8; ++i) {
        int row = bm + ty * 8 + i;
#pragma unroll
        for (int j = 0; j < 8; ++j) {
            int col = bn + tx * 8 + j;
            g_h[(size_t)row * OUTF + col] = acc[i][j] + bias[col];
        }
    }
}

// ============================================================
// column sums of g_h for batchnorm stats
// ============================================================
__global__ void colreduce_kernel() {
    const int c = threadIdx.x;          // 512 threads = 512 cols
    const int r0 = blockIdx.x * 256;    // 256 blocks x 256 rows
    float s = 0.f, s2 = 0.f;
    for (int r = r0; r < r0 + 256; ++r) {
        float v = g_h[(size_t)r * OUTF + c];
        s += v; s2 += v * v;
    }
    atomicAdd(&g_sum[c], s);
    atomicAdd(&g_sumsq[c], s2);
}

__global__ void finalize_bn_kernel(const float* __restrict__ gamma,
                                   const float* __restrict__ beta) {
    int c = threadIdx.x;
    float mu  = g_sum[c]   * (1.0f / NTOT);
    float var = g_sumsq[c] * (1.0f / NTOT) - mu * mu;
    float rs  = 1.0f / sqrtf(var + 1e-5f);
    float a   = gamma[c] * rs;
    g_a[c]  = a;
    g_b2[c] = beta[c] - mu * a;
}

// ============================================================
// squared norms of feature rows (for knn distance)
// one warp per row, 8 warps / block
// ============================================================
__global__ void xnorm_kernel(const float* __restrict__ F) {
    int row  = blockIdx.x * 8 + (threadIdx.x >> 5);
    int lane = threadIdx.x & 31;
    const float* r = F + (size_t)row * INF_;
    float s = 0.f;
#pragma unroll
    for (int i = 0; i < 2; ++i) {
        float4 v = *(const float4*)(r + lane * 8 + i * 4);
        s += v.x * v.x + v.y * v.y + v.z * v.z + v.w * v.w;
    }
#pragma unroll
    for (int off = 16; off > 0; off >>= 1) s += __shfl_xor_sync(0xffffffffu, s, off);
    if (lane == 0) g_xnorm[row] = s;
}

// ============================================================
// KNN GEMM per cloud: dist[1024,4096] = -2 * Q @ X^T + xnorm
// Q rows are gathered via fps indices. Same 128x128x16 tiling.
// grid: (4096/128, 1024/128, 16)
// ============================================================
__global__ __launch_bounds__(256) void knn_gemm_kernel(const float* __restrict__ F) {
    __shared__ float As[BK][BM];
    __shared__ float Bs[BK][BN];
    __shared__ int   s_rows[BM];
    const int c  = blockIdx.z;
    const int bm = blockIdx.y * BM;   // query tile
    const int bn = blockIdx.x * BN;   // point tile
    const int tid = threadIdx.x;
    const int tx = tid & 15, ty = tid >> 4;

    if (tid < BM) s_rows[tid] = c * Pc + g_fps[c * Sc + bm + tid];
    __syncthreads();

    float acc[8][8];
#pragma unroll
    for (int i = 0; i < 8; ++i)
#pragma unroll
        for (int j = 0; j < 8; ++j) acc[i][j] = 0.f;

    for (int k0 = 0; k0 < INF_; k0 += BK) {
#pragma unroll
        for (int it = 0; it < 2; ++it) {
            int f = tid + it * 256;
            int r = f >> 2, kq = (f & 3) * 4;
            float4 v = *(const float4*)(F + (size_t)s_rows[r] * INF_ + k0 + kq);
            As[kq + 0][r] = v.x; As[kq + 1][r] = v.y;
            As[kq + 2][r] = v.z; As[kq + 3][r] = v.w;
        }
#pragma unroll
        for (int it = 0; it < 2; ++it) {
            int f = tid + it * 256;
            int r = f >> 2, kq = (f & 3) * 4;
            float4 v = *(const float4*)(F + (size_t)(c * Pc + bn + r) * INF_ + k0 + kq);
            Bs[kq + 0][r] = v.x; Bs[kq + 1][r] = v.y;
            Bs[kq + 2][r] = v.z; Bs[kq + 3][r] = v.w;
        }
        __syncthreads();
#pragma unroll
        for (int kk = 0; kk < BK; ++kk) {
            float ra[8], rb[8];
#pragma unroll
            for (int i = 0; i < 8; ++i) ra[i] = As[kk][ty * 8 + i];
#pragma unroll
            for (int j = 0; j < 8; ++j) rb[j] = Bs[kk][tx * 8 + j];
#pragma unroll
            for (int i = 0; i < 8; ++i)
#pragma unroll
                for (int j = 0; j < 8; ++j) acc[i][j] += ra[i] * rb[j];
        }
        __syncthreads();
    }
#pragma unroll
    for (int i = 0; i < 8; ++i) {
        int q = c * Sc + bm + ty * 8 + i;
#pragma unroll
        for (int j = 0; j < 8; ++j) {
            int n = bn + tx * 8 + j;
            g_dist[(size_t)q * Pc + n] = -2.f * acc[i][j] + g_xnorm[c * Pc + n];
        }
    }
}

// ============================================================
// top-16 smallest per query: one warp per query.
// lane-local sorted top-16, then warp multiway merge.
// ============================================================
__global__ __launch_bounds__(256) void select_kernel() {
    const int q    = blockIdx.x * 8 + (threadIdx.x >> 5);
    const int lane = threadIdx.x & 31;
    const float* row = g_dist + (size_t)q * Pc;

    float bd[16];
    int   bi[16];
#pragma unroll
    for (int j = 0; j < 16; ++j) { bd[j] = 1e30f; bi[j] = 0x7fffffff; }

#pragma unroll 1
    for (int it = 0; it < Pc / 32; ++it) {
        int   i = it * 32 + lane;
        float v = row[i];
        if (v < bd[15]) {
            float cv = v; int ci = i;
#pragma unroll
            for (int j = 0; j < 16; ++j) {
                if (cv < bd[j]) {
                    float tv = bd[j]; int ti = bi[j];
                    bd[j] = cv; bi[j] = ci; cv = tv; ci = ti;
                }
            }
        }
    }

    const int cbase = (q >> 10) * Pc;   // cloud * P
#pragma unroll 1
    for (int r = 0; r < Kc; ++r) {
        float v = bd[0]; int idx = bi[0];
#pragma unroll
        for (int off = 16; off > 0; off >>= 1) {
            float ov = __shfl_xor_sync(0xffffffffu, v, off);
            int   oi = __shfl_xor_sync(0xffffffffu, idx, off);
            if (ov < v || (ov == v && oi < idx)) { v = ov; idx = oi; }
        }
        if (bi[0] == idx) {   // indices are unique -> exactly one winner lane
#pragma unroll
            for (int j = 0; j < 15; ++j) { bd[j] = bd[j + 1]; bi[j] = bi[j + 1]; }
            bd[15] = 1e30f; bi[15] = 0x7fffffff;
        }
        if (lane == 0) g_knn[q * Kc + r] = cbase + idx;
    }
}

// ============================================================
// max-pool over K neighbors + batchnorm affine + relu.
// relu(a*h+b2) is monotone in h per channel (sign of a) -> pool raw h.
// one block per query, 128 threads x 4 cols.
// ============================================================
__global__ __launch_bounds__(128) void pool_kernel(float* __restrict__ out_nf) {
    const int q   = blockIdx.x;
    const int tid = threadIdx.x;
    __shared__ int rows[Kc];
    if (tid < Kc) rows[tid] = g_knn[q * Kc + tid];
    __syncthreads();

    float mx[4], mn[4];
#pragma unroll
    for (int j = 0; j < 4; ++j) { mx[j] = -1e30f; mn[j] = 1e30f; }

#pragma unroll 1
    for (int k = 0; k < Kc; ++k) {
        const float* hr = g_h + (size_t)rows[k] * OUTF;
#pragma unroll
        for (int j = 0; j < 4; ++j) {
            float v = hr[tid + j * 128];
            mx[j] = fmaxf(mx[j], v);
            mn[j] = fminf(mn[j], v);
        }
    }
#pragma unroll
    for (int j = 0; j < 4; ++j) {
        int c = tid + j * 128;
        float a = g_a[c];
        float m = (a >= 0.f) ? mx[j] : mn[j];
        out_nf[(size_t)q * OUTF + c] = fmaxf(a * m + g_b2[c], 0.f);
    }
}

// ============================================================
// launch
// ============================================================
extern "C" void kernel_launch(void* const* d_in, const int* in_sizes, int n_in,
                              void* d_out, int out_size) {
    const float* features  = (const float*)d_in[0];
    const float* positions = (const float*)d_in[1];
    /* d_in[2] = batch (int32), derivable */
    const float* W     = (const float*)d_in[3];
    const float* bias  = (const float*)d_in[4];
    const float* gamma = (const float*)d_in[5];
    const float* beta  = (const float*)d_in[6];

    float* out = (float*)d_out;
    const long long nf_elems   = (long long)QTOT * OUTF;           // 8388608
    const long long pos_elems  = (long long)QTOT * 3;              // 49152
    int write_pos   = (out_size >= nf_elems + pos_elems) ? 1 : 0;
    int write_batch = (out_size >= nf_elems + pos_elems + QTOT) ? 1 : 0;
    float* out_pos   = out + nf_elems;
    float* out_batch = out + nf_elems + pos_elems;

    zero_sums_kernel<<<1, OUTF>>>();
    fps_kernel<<<Bc, 256>>>(positions, out_pos, out_batch, write_pos, write_batch);
    gemm_mlp_kernel<<<dim3(OUTF / BN, NTOT / BM), 256>>>(features, W, bias);
    colreduce_kernel<<<NTOT / 256, OUTF>>>();
    finalize_bn_kernel<<<1, OUTF>>>(gamma, beta);
    xnorm_kernel<<<NTOT / 8, 256>>>(features);
    knn_gemm_kernel<<<dim3(Pc / BN, Sc / BM, Bc), 256>>>(features);
    select_kernel<<<QTOT / 8, 256>>>();
    pool_kernel<<<QTOT, 128>>>(out);
}

// round 3
// speedup vs baseline: 1.4345x; 1.4345x over previous
#include <cuda_runtime.h>
#include <cuda_bf16.h>
#include <cstdint>

#define Bc   16
#define Pc   4096
#define Sc   1024
#define Kc   16
#define INF_ 256
#define OUTF 512
#define NTOT (Bc * Pc)   // 65536
#define QTOT (Bc * Sc)   // 16384

// ---- scratch (device globals; no runtime allocation allowed) ----
__device__ float g_h[(size_t)NTOT * OUTF];      // 128 MB
__device__ float g_dist[(size_t)QTOT * Pc];     // 256 MB
__device__ int   g_fps[QTOT];
__device__ int   g_knn[QTOT * Kc];
__device__ float g_sum[OUTF];
__device__ float g_sumsq[OUTF];
__device__ float g_a[OUTF];
__device__ float g_b2[OUTF];
__device__ float g_xnorm[NTOT];
__device__ __nv_bfloat16 g_fhi[(size_t)NTOT * INF_];
__device__ __nv_bfloat16 g_flo[(size_t)NTOT * INF_];
__device__ __nv_bfloat16 g_wthi[(size_t)OUTF * INF_];  // W^T [512,256]
__device__ __nv_bfloat16 g_wtlo[(size_t)OUTF * INF_];

// ============================================================
// mma helpers
// ============================================================
__device__ __forceinline__ uint32_t smem_u32(const void* p) {
    uint32_t a;
    asm("{ .reg .u64 t; cvta.to.shared.u64 t, %1; cvt.u32.u64 %0, t; }" : "=r"(a) : "l"(p));
    return a;
}
__device__ __forceinline__ void ldsm4(uint32_t& r0, uint32_t& r1, uint32_t& r2, uint32_t& r3,
                                      uint32_t addr) {
    asm volatile("ldmatrix.sync.aligned.m8n8.x4.shared.b16 {%0,%1,%2,%3}, [%4];"
                 : "=r"(r0), "=r"(r1), "=r"(r2), "=r"(r3) : "r"(addr));
}
__device__ __forceinline__ void mma16816(float* c, const uint32_t* a, const uint32_t* b) {
    asm volatile(
        "mma.sync.aligned.m16n8k16.row.col.f32.bf16.bf16.f32 "
        "{%0,%1,%2,%3}, {%4,%5,%6,%7}, {%8,%9}, {%0,%1,%2,%3};"
        : "+f"(c[0]), "+f"(c[1]), "+f"(c[2]), "+f"(c[3])
        : "r"(a[0]), "r"(a[1]), "r"(a[2]), "r"(a[3]), "r"(b[0]), "r"(b[1]));
}

#define STRB 48                      // smem bytes per row (16 bf16 + pad) -> conflict-free ldmatrix
#define TILEB (128 * STRB)           // 6144 bytes per tile

// ============================================================
// prep: fp32 -> bf16 hi/lo splits
// ============================================================
__global__ void prep_f_kernel(const float* __restrict__ F) {
    size_t i = (size_t)blockIdx.x * INF_ + threadIdx.x;
    float v = F[i];
    __nv_bfloat16 h = __float2bfloat16(v);
    g_fhi[i] = h;
    g_flo[i] = __float2bfloat16(v - __bfloat162float(h));
}
__global__ void prep_w_kernel(const float* __restrict__ W) {
    int n = blockIdx.x, k = threadIdx.x;
    float v = W[(size_t)k * OUTF + n];
    __nv_bfloat16 h = __float2bfloat16(v);
    g_wthi[(size_t)n * INF_ + k] = h;
    g_wtlo[(size_t)n * INF_ + k] = __float2bfloat16(v - __bfloat162float(h));
}

__global__ void zero_sums_kernel() {
    int t = threadIdx.x;
    if (t < OUTF) { g_sum[t] = 0.f; g_sumsq[t] = 0.f; }
}

// ============================================================
// FPS (bit-exact XLA arithmetic, proven R1)
// ============================================================
__global__ void fps_kernel(const float* __restrict__ pos,
                           float* __restrict__ out_pos,
                           float* __restrict__ out_batch,
                           int write_pos, int write_batch) {
    const int c = blockIdx.x, tid = threadIdx.x;
    const int wid = tid >> 5, lane = tid & 31;
    const float* p = pos + (size_t)c * Pc * 3;

    float px[16], py[16], pz[16], md[16];
#pragma unroll
    for (int j = 0; j < 16; ++j) {
        int i = tid + j * 256;
        px[j] = p[i * 3 + 0]; py[j] = p[i * 3 + 1]; pz[j] = p[i * 3 + 2];
        md[j] = 3.402823466e+38f;
    }
    __shared__ float s_val[8];
    __shared__ int   s_idx[8];
    __shared__ int   s_last;
    int last = 0;
    if (tid == 0) g_fps[c * Sc + 0] = 0;

    for (int t = 1; t < Sc; ++t) {
        float lx = p[last * 3 + 0], ly = p[last * 3 + 1], lz = p[last * 3 + 2];
        float bestv = -1.0f; int besti = 0x7fffffff;
#pragma unroll
        for (int j = 0; j < 16; ++j) {
            float dx = __fsub_rn(px[j], lx);
            float dy = __fsub_rn(py[j], ly);
            float dz = __fsub_rn(pz[j], lz);
            float d = __fadd_rn(__fadd_rn(__fmul_rn(dx, dx), __fmul_rn(dy, dy)),
                                __fmul_rn(dz, dz));
            md[j] = fminf(md[j], d);
            int idx = tid + j * 256;
            if (md[j] > bestv || (md[j] == bestv && idx < besti)) { bestv = md[j]; besti = idx; }
        }
#pragma unroll
        for (int off = 16; off > 0; off >>= 1) {
            float ov = __shfl_xor_sync(0xffffffffu, bestv, off);
            int   oi = __shfl_xor_sync(0xffffffffu, besti, off);
            if (ov > bestv || (ov == bestv && oi < besti)) { bestv = ov; besti = oi; }
        }
        if (lane == 0) { s_val[wid] = bestv; s_idx[wid] = besti; }
        __syncthreads();
        if (wid == 0) {
            float v = (lane < 8) ? s_val[lane] : -1.0f;
            int   i = (lane < 8) ? s_idx[lane] : 0x7fffffff;
#pragma unroll
            for (int off = 4; off > 0; off >>= 1) {
                float ov = __shfl_xor_sync(0xffffffffu, v, off);
                int   oi = __shfl_xor_sync(0xffffffffu, i, off);
                if (ov > v || (ov == v && oi < i)) { v = ov; i = oi; }
            }
            if (lane == 0) { s_last = i; g_fps[c * Sc + t] = i; }
        }
        __syncthreads();
        last = s_last;
    }
    for (int s = tid; s < Sc; s += 256) {
        int li = g_fps[c * Sc + s];
        int q = c * Sc + s;
        if (write_pos) {
            out_pos[q * 3 + 0] = p[li * 3 + 0];
            out_pos[q * 3 + 1] = p[li * 3 + 1];
            out_pos[q * 3 + 2] = p[li * 3 + 2];
        }
        if (write_batch) out_batch[q] = (float)c;
    }
}

// ============================================================
// HMMA bf16-split GEMM: MLP   g_h = F @ W + b
// block 128x128, BK=16, 8 warps (4m x 2n), warp tile 32x64
// ============================================================
__global__ __launch_bounds__(256, 2) void mlp_mma_kernel(const float* __restrict__ bias) {
    __shared__ __align__(16) char smbuf[4 * TILEB];
    const uint32_t sAh = smem_u32(smbuf);
    const uint32_t sAl = sAh + TILEB;
    const uint32_t sBh = sAh + 2 * TILEB;
    const uint32_t sBl = sAh + 3 * TILEB;

    const int tid = threadIdx.x, lane = tid & 31, wid = tid >> 5;
    const int warp_m = wid & 3, warp_n = wid >> 2;
    const int bm = blockIdx.y * 128, bn = blockIdx.x * 128;

    float acc[2][8][4];
#pragma unroll
    for (int i = 0; i < 2; ++i)
#pragma unroll
        for (int j = 0; j < 8; ++j)
#pragma unroll
            for (int l = 0; l < 4; ++l) acc[i][j][l] = 0.f;

    const int lr = tid >> 1, lh = tid & 1;              // loader: row, 16B-half
    const uint32_t soff = lr * STRB + lh * 16;
    const uint32_t lmoff = (lane & 15) * STRB + (lane >> 4) * 16;

    for (int k0 = 0; k0 < INF_; k0 += 16) {
        __syncthreads();
        {
            size_t ai = (size_t)(bm + lr) * INF_ + k0 + lh * 8;
            size_t bi = (size_t)(bn + lr) * INF_ + k0 + lh * 8;
            *(uint4*)(smbuf + 0 * TILEB + soff) = *(const uint4*)(g_fhi + ai);
            *(uint4*)(smbuf + 1 * TILEB + soff) = *(const uint4*)(g_flo + ai);
            *(uint4*)(smbuf + 2 * TILEB + soff) = *(const uint4*)(g_wthi + bi);
            *(uint4*)(smbuf + 3 * TILEB + soff) = *(const uint4*)(g_wtlo + bi);
        }
        __syncthreads();

        uint32_t ah[2][4], al[2][4];
#pragma unroll
        for (int mt = 0; mt < 2; ++mt) {
            uint32_t base = (warp_m * 32 + mt * 16) * STRB + lmoff;
            ldsm4(ah[mt][0], ah[mt][1], ah[mt][2], ah[mt][3], sAh + base);
            ldsm4(al[mt][0], al[mt][1], al[mt][2], al[mt][3], sAl + base);
        }
#pragma unroll
        for (int np2 = 0; np2 < 4; ++np2) {
            uint32_t base = (warp_n * 64 + np2 * 16) * STRB + lmoff;
            uint32_t h0, h1, h2, h3, l0, l1, l2, l3;
            ldsm4(h0, h1, h2, h3, sBh + base);
            ldsm4(l0, l1, l2, l3, sBl + base);
            uint32_t bh0[2] = {h0, h2}, bh1[2] = {h1, h3};
            uint32_t bl0[2] = {l0, l2}, bl1[2] = {l1, l3};
#pragma unroll
            for (int mt = 0; mt < 2; ++mt) {
                mma16816(acc[mt][np2 * 2 + 0], ah[mt], bh0);
                mma16816(acc[mt][np2 * 2 + 0], ah[mt], bl0);
                mma16816(acc[mt][np2 * 2 + 0], al[mt], bh0);
                mma16816(acc[mt][np2 * 2 + 1], ah[mt], bh1);
                mma16816(acc[mt][np2 * 2 + 1], ah[mt], bl1);
                mma16816(acc[mt][np2 * 2 + 1], al[mt], bh1);
            }
        }
    }

#pragma unroll
    for (int mt = 0; mt < 2; ++mt) {
        int row = bm + warp_m * 32 + mt * 16 + (lane >> 2);
#pragma unroll
        for (int nt = 0; nt < 8; ++nt) {
            int col = bn + warp_n * 64 + nt * 8 + (lane & 3) * 2;
            float b0 = bias[col], b1 = bias[col + 1];
            float2 v0 = {acc[mt][nt][0] + b0, acc[mt][nt][1] + b1};
            float2 v1 = {acc[mt][nt][2] + b0, acc[mt][nt][3] + b1};
            *(float2*)(g_h + (size_t)row * OUTF + col) = v0;
            *(float2*)(g_h + (size_t)(row + 8) * OUTF + col) = v1;
        }
    }
}

// ============================================================
// HMMA bf16-split GEMM: KNN   g_dist = -2 Q.X^T + |x|^2
// grid (Pc/128, Sc/128, Bc)
// ============================================================
__global__ __launch_bounds__(256, 2) void knn_mma_kernel() {
    __shared__ __align__(16) char smbuf[4 * TILEB];
    __shared__ int s_rows[128];
    const uint32_t sAh = smem_u32(smbuf);
    const uint32_t sAl = sAh + TILEB;
    const uint32_t sBh = sAh + 2 * TILEB;
    const uint32_t sBl = sAh + 3 * TILEB;

    const int tid = threadIdx.x, lane = tid & 31, wid = tid >> 5;
    const int warp_m = wid & 3, warp_n = wid >> 2;
    const int c = blockIdx.z;
    const int bm = blockIdx.y * 128;   // query tile
    const int bn = blockIdx.x * 128;   // point tile

    if (tid < 128) s_rows[tid] = c * Pc + g_fps[c * Sc + bm + tid];

    float acc[2][8][4];
#pragma unroll
    for (int i = 0; i < 2; ++i)
#pragma unroll
        for (int j = 0; j < 8; ++j)
#pragma unroll
            for (int l = 0; l < 4; ++l) acc[i][j][l] = 0.f;

    const int lr = tid >> 1, lh = tid & 1;
    const uint32_t soff = lr * STRB + lh * 16;
    const uint32_t lmoff = (lane & 15) * STRB + (lane >> 4) * 16;
    __syncthreads();   // s_rows visible
    const size_t arow = (size_t)s_rows[lr] * INF_;
    const size_t brow = (size_t)(c * Pc + bn + lr) * INF_;

    for (int k0 = 0; k0 < INF_; k0 += 16) {
        __syncthreads();
        {
            size_t ai = arow + k0 + lh * 8;
            size_t bi = brow + k0 + lh * 8;
            *(uint4*)(smbuf + 0 * TILEB + soff) = *(const uint4*)(g_fhi + ai);
            *(uint4*)(smbuf + 1 * TILEB + soff) = *(const uint4*)(g_flo + ai);
            *(uint4*)(smbuf + 2 * TILEB + soff) = *(const uint4*)(g_fhi + bi);
            *(uint4*)(smbuf + 3 * TILEB + soff) = *(const uint4*)(g_flo + bi);
        }
        __syncthreads();

        uint32_t ah[2][4], al[2][4];
#pragma unroll
        for (int mt = 0; mt < 2; ++mt) {
            uint32_t base = (warp_m * 32 + mt * 16) * STRB + lmoff;
            ldsm4(ah[mt][0], ah[mt][1], ah[mt][2], ah[mt][3], sAh + base);
            ldsm4(al[mt][0], al[mt][1], al[mt][2], al[mt][3], sAl + base);
        }
#pragma unroll
        for (int np2 = 0; np2 < 4; ++np2) {
            uint32_t base = (warp_n * 64 + np2 * 16) * STRB + lmoff;
            uint32_t h0, h1, h2, h3, l0, l1, l2, l3;
            ldsm4(h0, h1, h2, h3, sBh + base);
            ldsm4(l0, l1, l2, l3, sBl + base);
            uint32_t bh0[2] = {h0, h2}, bh1[2] = {h1, h3};
            uint32_t bl0[2] = {l0, l2}, bl1[2] = {l1, l3};
#pragma unroll
            for (int mt = 0; mt < 2; ++mt) {
                mma16816(acc[mt][np2 * 2 + 0], ah[mt], bh0);
                mma16816(acc[mt][np2 * 2 + 0], ah[mt], bl0);
                mma16816(acc[mt][np2 * 2 + 0], al[mt], bh0);
                mma16816(acc[mt][np2 * 2 + 1], ah[mt], bh1);
                mma16816(acc[mt][np2 * 2 + 1], ah[mt], bl1);
                mma16816(acc[mt][np2 * 2 + 1], al[mt], bh1);
            }
        }
    }

#pragma unroll
    for (int mt = 0; mt < 2; ++mt) {
        int q = c * Sc + bm + warp_m * 32 + mt * 16 + (lane >> 2);
#pragma unroll
        for (int nt = 0; nt < 8; ++nt) {
            int col = bn + warp_n * 64 + nt * 8 + (lane & 3) * 2;
            float x0 = g_xnorm[c * Pc + col], x1 = g_xnorm[c * Pc + col + 1];
            float2 v0 = {-2.f * acc[mt][nt][0] + x0, -2.f * acc[mt][nt][1] + x1};
            float2 v1 = {-2.f * acc[mt][nt][2] + x0, -2.f * acc[mt][nt][3] + x1};
            *(float2*)(g_dist + (size_t)q * Pc + col) = v0;
            *(float2*)(g_dist + (size_t)(q + 8) * Pc + col) = v1;
        }
    }
}

// ============================================================
// batchnorm stats + finalize
// ============================================================
__global__ void colreduce_kernel() {
    const int c = threadIdx.x;
    const int r0 = blockIdx.x * 256;
    float s = 0.f, s2 = 0.f;
    for (int r = r0; r < r0 + 256; ++r) {
        float v = g_h[(size_t)r * OUTF + c];
        s += v; s2 += v * v;
    }
    atomicAdd(&g_sum[c], s);
    atomicAdd(&g_sumsq[c], s2);
}
__global__ void finalize_bn_kernel(const float* __restrict__ gamma,
                                   const float* __restrict__ beta) {
    int c = threadIdx.x;
    float mu  = g_sum[c]   * (1.0f / NTOT);
    float var = g_sumsq[c] * (1.0f / NTOT) - mu * mu;
    float rs  = 1.0f / sqrtf(var + 1e-5f);
    float a   = gamma[c] * rs;
    g_a[c] = a;
    g_b2[c] = beta[c] - mu * a;
}

__global__ void xnorm_kernel(const float* __restrict__ F) {
    int row = blockIdx.x * 8 + (threadIdx.x >> 5);
    int lane = threadIdx.x & 31;
    const float* r = F + (size_t)row * INF_;
    float s = 0.f;
#pragma unroll
    for (int i = 0; i < 2; ++i) {
        float4 v = *(const float4*)(r + lane * 8 + i * 4);
        s += v.x * v.x + v.y * v.y + v.z * v.z + v.w * v.w;
    }
#pragma unroll
    for (int off = 16; off > 0; off >>= 1) s += __shfl_xor_sync(0xffffffffu, s, off);
    if (lane == 0) g_xnorm[row] = s;
}

// ============================================================
// top-16 select (proven R1)
// ============================================================
__global__ __launch_bounds__(256) void select_kernel() {
    const int q = blockIdx.x * 8 + (threadIdx.x >> 5);
    const int lane = threadIdx.x & 31;
    const float* row = g_dist + (size_t)q * Pc;

    float bd[16]; int bi[16];
#pragma unroll
    for (int j = 0; j < 16; ++j) { bd[j] = 1e30f; bi[j] = 0x7fffffff; }
#pragma unroll 1
    for (int it = 0; it < Pc / 32; ++it) {
        int i = it * 32 + lane;
        float v = row[i];
        if (v < bd[15]) {
            float cv = v; int ci = i;
#pragma unroll
            for (int j = 0; j < 16; ++j) {
                if (cv < bd[j]) {
                    float tv = bd[j]; int ti = bi[j];
                    bd[j] = cv; bi[j] = ci; cv = tv; ci = ti;
                }
            }
        }
    }
    const int cbase = (q >> 10) * Pc;
#pragma unroll 1
    for (int r = 0; r < Kc; ++r) {
        float v = bd[0]; int idx = bi[0];
#pragma unroll
        for (int off = 16; off > 0; off >>= 1) {
            float ov = __shfl_xor_sync(0xffffffffu, v, off);
            int   oi = __shfl_xor_sync(0xffffffffu, idx, off);
            if (ov < v || (ov == v && oi < idx)) { v = ov; idx = oi; }
        }
        if (bi[0] == idx) {
#pragma unroll
            for (int j = 0; j < 15; ++j) { bd[j] = bd[j + 1]; bi[j] = bi[j + 1]; }
            bd[15] = 1e30f; bi[15] = 0x7fffffff;
        }
        if (lane == 0) g_knn[q * Kc + r] = cbase + idx;
    }
}

// ============================================================
// max-pool + BN affine + relu
// ============================================================
__global__ __launch_bounds__(128) void pool_kernel(float* __restrict__ out_nf) {
    const int q = blockIdx.x, tid = threadIdx.x;
    __shared__ int rows[Kc];
    if (tid < Kc) rows[tid] = g_knn[q * Kc + tid];
    __syncthreads();

    float mx[4], mn[4];
#pragma unroll
    for (int j = 0; j < 4; ++j) { mx[j] = -1e30f; mn[j] = 1e30f; }
#pragma unroll 1
    for (int k = 0; k < Kc; ++k) {
        const float* hr = g_h + (size_t)rows[k] * OUTF;
#pragma unroll
        for (int j = 0; j < 4; ++j) {
            float v = hr[tid + j * 128];
            mx[j] = fmaxf(mx[j], v);
            mn[j] = fminf(mn[j], v);
        }
    }
#pragma unroll
    for (int j = 0; j < 4; ++j) {
        int c = tid + j * 128;
        float a = g_a[c];
        float m = (a >= 0.f) ? mx[j] : mn[j];
        out_nf[(size_t)q * OUTF + c] = fmaxf(a * m + g_b2[c], 0.f);
    }
}

// ============================================================
// launch
// ============================================================
extern "C" void kernel_launch(void* const* d_in, const int* in_sizes, int n_in,
                              void* d_out, int out_size) {
    const float* features  = (const float*)d_in[0];
    const float* positions = (const float*)d_in[1];
    const float* W     = (const float*)d_in[3];
    const float* bias  = (const float*)d_in[4];
    const float* gamma = (const float*)d_in[5];
    const float* beta  = (const float*)d_in[6];

    float* out = (float*)d_out;
    const long long nf_elems  = (long long)QTOT * OUTF;
    const long long pos_elems = (long long)QTOT * 3;
    int write_pos   = (out_size >= nf_elems + pos_elems) ? 1 : 0;
    int write_batch = (out_size >= nf_elems + pos_elems + QTOT) ? 1 : 0;
    float* out_pos   = out + nf_elems;
    float* out_batch = out + nf_elems + pos_elems;

    zero_sums_kernel<<<1, OUTF>>>();
    prep_f_kernel<<<NTOT, INF_>>>(features);
    prep_w_kernel<<<OUTF, INF_>>>(W);
    xnorm_kernel<<<NTOT / 8, 256>>>(features);
    fps_kernel<<<Bc, 256>>>(positions, out_pos, out_batch, write_pos, write_batch);
    mlp_mma_kernel<<<dim3(OUTF / 128, NTOT / 128), 256>>>(bias);
    colreduce_kernel<<<NTOT / 256, OUTF>>>();
    finalize_bn_kernel<<<1, OUTF>>>(gamma, beta);
    knn_mma_kernel<<<dim3(Pc / 128, Sc / 128, Bc), 256>>>();
    select_kernel<<<QTOT / 8, 256>>>();
    pool_kernel<<<QTOT, 128>>>(out);
}

// round 4
// speedup vs baseline: 1.8054x; 1.2586x over previous
#include <cuda_runtime.h>
#include <cuda_fp16.h>
#include <cuda_bf16.h>
#include <cstdint>

#define Bc   16
#define Pc   4096
#define Sc   1024
#define Kc   16
#define INF_ 256
#define OUTF 512
#define NTOT (Bc * Pc)   // 65536
#define QTOT (Bc * Sc)   // 16384
#define NCAND 24

// ---- scratch (device globals) ----
__device__ float  g_h[(size_t)NTOT * OUTF];       // 128 MB
__device__ __half g_dist16[(size_t)QTOT * Pc];    // 128 MB coarse distances
__device__ int    g_fps[QTOT];
__device__ int    g_knn[QTOT * Kc];
__device__ int    g_cand[QTOT * NCAND];
__device__ float  g_sum[OUTF];
__device__ float  g_sumsq[OUTF];
__device__ float  g_a[OUTF];
__device__ float  g_b2[OUTF];
__device__ float  g_xnorm[NTOT];
__device__ __nv_bfloat16 g_fhi[(size_t)NTOT * INF_];   // 32 MB (KNN coarse)
__device__ float  g_wt32hi[(size_t)OUTF * INF_];       // W^T tf32-hi (fp32 enc)
__device__ float  g_wt32lo[(size_t)OUTF * INF_];       // W^T tf32-lo

// ============================================================
// helpers
// ============================================================
__device__ __forceinline__ uint32_t smem_u32(const void* p) {
    uint32_t a;
    asm("{ .reg .u64 t; cvta.to.shared.u64 t, %1; cvt.u32.u64 %0, t; }" : "=r"(a) : "l"(p));
    return a;
}
__device__ __forceinline__ void ldsm4(uint32_t& r0, uint32_t& r1, uint32_t& r2, uint32_t& r3,
                                      uint32_t addr) {
    asm volatile("ldmatrix.sync.aligned.m8n8.x4.shared.b16 {%0,%1,%2,%3}, [%4];"
                 : "=r"(r0), "=r"(r1), "=r"(r2), "=r"(r3) : "r"(addr));
}
__device__ __forceinline__ void mma16816(float* c, const uint32_t* a, const uint32_t* b) {
    asm volatile(
        "mma.sync.aligned.m16n8k16.row.col.f32.bf16.bf16.f32 "
        "{%0,%1,%2,%3}, {%4,%5,%6,%7}, {%8,%9}, {%0,%1,%2,%3};"
        : "+f"(c[0]), "+f"(c[1]), "+f"(c[2]), "+f"(c[3])
        : "r"(a[0]), "r"(a[1]), "r"(a[2]), "r"(a[3]), "r"(b[0]), "r"(b[1]));
}
__device__ __forceinline__ void mma1688_tf32(float* c, const uint32_t* a, const uint32_t* b) {
    asm volatile(
        "mma.sync.aligned.m16n8k8.row.col.f32.tf32.tf32.f32 "
        "{%0,%1,%2,%3}, {%4,%5,%6,%7}, {%8,%9}, {%0,%1,%2,%3};"
        : "+f"(c[0]), "+f"(c[1]), "+f"(c[2]), "+f"(c[3])
        : "r"(a[0]), "r"(a[1]), "r"(a[2]), "r"(a[3]), "r"(b[0]), "r"(b[1]));
}
__device__ __forceinline__ float tf32_rna(float v) {
    uint32_t u;
    asm("cvt.rna.tf32.f32 %0, %1;" : "=r"(u) : "f"(v));
    return __uint_as_float(u);
}

#define STRB 48                      // knn smem row stride (bytes)
#define TILEB (128 * STRB)
#define ASTR 12                      // mlp smem row stride (floats): 8 data + 4 pad

// ============================================================
// zero + prep_w (W^T tf32 hi/lo)
// ============================================================
__global__ void zero_sums_kernel() {
    int t = threadIdx.x;
    if (t < OUTF) { g_sum[t] = 0.f; g_sumsq[t] = 0.f; }
}
__global__ void prep_w_kernel(const float* __restrict__ W) {
    int n = blockIdx.x, k = threadIdx.x;
    float v = W[(size_t)k * OUTF + n];
    float hi = tf32_rna(v);
    float lo = tf32_rna(v - hi);
    g_wt32hi[(size_t)n * INF_ + k] = hi;
    g_wt32lo[(size_t)n * INF_ + k] = lo;
}

// ============================================================
// FAT kernel: [0,16) FPS | [16,272) prepF+xnorm | [272,2320) MLP tf32
// ============================================================
#define FPS_BLKS  16
#define PREP_BLKS 256
#define MLP_BLKS  2048
#define FAT_GRID  (FPS_BLKS + PREP_BLKS + MLP_BLKS)

__global__ __launch_bounds__(256, 2) void fat_kernel(
    const float* __restrict__ F, const float* __restrict__ pos,
    const float* __restrict__ bias,
    float* __restrict__ out_pos, float* __restrict__ out_batch,
    int write_pos, int write_batch) {

    const int bid = blockIdx.x;
    const int tid = threadIdx.x;
    const int lane = tid & 31, wid = tid >> 5;

    if (bid < FPS_BLKS) {
        // ---------------- FPS (bit-exact R1 code) ----------------
        const int c = bid;
        const float* p = pos + (size_t)c * Pc * 3;
        float px[16], py[16], pz[16], md[16];
#pragma unroll
        for (int j = 0; j < 16; ++j) {
            int i = tid + j * 256;
            px[j] = p[i * 3 + 0]; py[j] = p[i * 3 + 1]; pz[j] = p[i * 3 + 2];
            md[j] = 3.402823466e+38f;
        }
        __shared__ float s_val[8];
        __shared__ int   s_idx[8];
        __shared__ int   s_last;
        int last = 0;
        if (tid == 0) g_fps[c * Sc + 0] = 0;

        for (int t = 1; t < Sc; ++t) {
            float lx = p[last * 3 + 0], ly = p[last * 3 + 1], lz = p[last * 3 + 2];
            float bestv = -1.0f; int besti = 0x7fffffff;
#pragma unroll
            for (int j = 0; j < 16; ++j) {
                float dx = __fsub_rn(px[j], lx);
                float dy = __fsub_rn(py[j], ly);
                float dz = __fsub_rn(pz[j], lz);
                float d = __fadd_rn(__fadd_rn(__fmul_rn(dx, dx), __fmul_rn(dy, dy)),
                                    __fmul_rn(dz, dz));
                md[j] = fminf(md[j], d);
                int idx = tid + j * 256;
                if (md[j] > bestv || (md[j] == bestv && idx < besti)) { bestv = md[j]; besti = idx; }
            }
#pragma unroll
            for (int off = 16; off > 0; off >>= 1) {
                float ov = __shfl_xor_sync(0xffffffffu, bestv, off);
                int   oi = __shfl_xor_sync(0xffffffffu, besti, off);
                if (ov > bestv || (ov == bestv && oi < besti)) { bestv = ov; besti = oi; }
            }
            if (lane == 0) { s_val[wid] = bestv; s_idx[wid] = besti; }
            __syncthreads();
            if (wid == 0) {
                float v = (lane < 8) ? s_val[lane] : -1.0f;
                int   i = (lane < 8) ? s_idx[lane] : 0x7fffffff;
#pragma unroll
                for (int off = 4; off > 0; off >>= 1) {
                    float ov = __shfl_xor_sync(0xffffffffu, v, off);
                    int   oi = __shfl_xor_sync(0xffffffffu, i, off);
                    if (ov > v || (ov == v && oi < i)) { v = ov; i = oi; }
                }
                if (lane == 0) { s_last = i; g_fps[c * Sc + t] = i; }
            }
            __syncthreads();
            last = s_last;
        }
        for (int s = tid; s < Sc; s += 256) {
            int li = g_fps[c * Sc + s];
            int q = c * Sc + s;
            if (write_pos) {
                out_pos[q * 3 + 0] = p[li * 3 + 0];
                out_pos[q * 3 + 1] = p[li * 3 + 1];
                out_pos[q * 3 + 2] = p[li * 3 + 2];
            }
            if (write_batch) out_batch[q] = (float)c;
        }
        return;
    }

    if (bid < FPS_BLKS + PREP_BLKS) {
        // ---------------- prep_f (bf16 hi) + xnorm ----------------
        int row = (bid - FPS_BLKS) * 256 + tid;
        const float* src = F + (size_t)row * INF_;
        __nv_bfloat162* dst = (__nv_bfloat162*)(g_fhi + (size_t)row * INF_);
        float s = 0.f;
#pragma unroll 4
        for (int i = 0; i < 64; ++i) {
            float4 v = *(const float4*)(src + i * 4);
            dst[2 * i + 0] = __nv_bfloat162(__float2bfloat16(v.x), __float2bfloat16(v.y));
            dst[2 * i + 1] = __nv_bfloat162(__float2bfloat16(v.z), __float2bfloat16(v.w));
            s += v.x * v.x + v.y * v.y + v.z * v.z + v.w * v.w;
        }
        g_xnorm[row] = s;
        return;
    }

    // ---------------- MLP 3xTF32: g_h = F @ W + b ----------------
    {
        __shared__ float smA[2][128 * ASTR];   // hi, lo
        __shared__ float smB[2][128 * ASTR];

        const int mb = bid - (FPS_BLKS + PREP_BLKS);
        const int bn = (mb & 3) * 128;
        const int bm = (mb >> 2) * 128;
        const int wm = wid & 3, wn = wid >> 2;       // 4x2 warps
        const int lr4 = lane >> 2, lk = lane & 3;

        float acc[2][8][4];
#pragma unroll
        for (int i = 0; i < 2; ++i)
#pragma unroll
            for (int j = 0; j < 8; ++j)
#pragma unroll
                for (int l = 0; l < 4; ++l) acc[i][j][l] = 0.f;

        const int lrow = tid >> 1, lh = tid & 1;     // loader: row, col-half
        const int cg = lh * 4;

        float4 pa, pbh, pbl;
        {
            pa  = *(const float4*)(F + (size_t)(bm + lrow) * INF_ + cg);
            pbh = *(const float4*)(g_wt32hi + (size_t)(bn + lrow) * INF_ + cg);
            pbl = *(const float4*)(g_wt32lo + (size_t)(bn + lrow) * INF_ + cg);
        }

        for (int kc = 0; kc < 32; ++kc) {
            __syncthreads();
            {
                float av[4] = {pa.x, pa.y, pa.z, pa.w};
#pragma unroll
                for (int j = 0; j < 4; ++j) {
                    float hi = tf32_rna(av[j]);
                    float lo = tf32_rna(av[j] - hi);
                    smA[0][lrow * ASTR + cg + j] = hi;
                    smA[1][lrow * ASTR + cg + j] = lo;
                }
                float bh[4] = {pbh.x, pbh.y, pbh.z, pbh.w};
                float bl[4] = {pbl.x, pbl.y, pbl.z, pbl.w};
#pragma unroll
                for (int j = 0; j < 4; ++j) {
                    smB[0][lrow * ASTR + cg + j] = bh[j];
                    smB[1][lrow * ASTR + cg + j] = bl[j];
                }
            }
            __syncthreads();
            if (kc + 1 < 32) {
                int k0 = (kc + 1) * 8;
                pa  = *(const float4*)(F + (size_t)(bm + lrow) * INF_ + k0 + cg);
                pbh = *(const float4*)(g_wt32hi + (size_t)(bn + lrow) * INF_ + k0 + cg);
                pbl = *(const float4*)(g_wt32lo + (size_t)(bn + lrow) * INF_ + k0 + cg);
            }

            uint32_t ah[2][4], al[2][4];
#pragma unroll
            for (int mt = 0; mt < 2; ++mt) {
                int rb = wm * 32 + mt * 16 + lr4;
                ah[mt][0] = __float_as_uint(smA[0][rb * ASTR + lk]);
                ah[mt][1] = __float_as_uint(smA[0][(rb + 8) * ASTR + lk]);
                ah[mt][2] = __float_as_uint(smA[0][rb * ASTR + lk + 4]);
                ah[mt][3] = __float_as_uint(smA[0][(rb + 8) * ASTR + lk + 4]);
                al[mt][0] = __float_as_uint(smA[1][rb * ASTR + lk]);
                al[mt][1] = __float_as_uint(smA[1][(rb + 8) * ASTR + lk]);
                al[mt][2] = __float_as_uint(smA[1][rb * ASTR + lk + 4]);
                al[mt][3] = __float_as_uint(smA[1][(rb + 8) * ASTR + lk + 4]);
            }
#pragma unroll
            for (int nt = 0; nt < 8; ++nt) {
                int nb = wn * 64 + nt * 8 + lr4;
                uint32_t bh[2], bl[2];
                bh[0] = __float_as_uint(smB[0][nb * ASTR + lk]);
                bh[1] = __float_as_uint(smB[0][nb * ASTR + lk + 4]);
                bl[0] = __float_as_uint(smB[1][nb * ASTR + lk]);
                bl[1] = __float_as_uint(smB[1][nb * ASTR + lk + 4]);
#pragma unroll
                for (int mt = 0; mt < 2; ++mt) {
                    mma1688_tf32(acc[mt][nt], ah[mt], bh);
                    mma1688_tf32(acc[mt][nt], ah[mt], bl);
                    mma1688_tf32(acc[mt][nt], al[mt], bh);
                }
            }
        }

#pragma unroll
        for (int mt = 0; mt < 2; ++mt) {
            int row = bm + wm * 32 + mt * 16 + lr4;
#pragma unroll
            for (int nt = 0; nt < 8; ++nt) {
                int col = bn + wn * 64 + nt * 8 + 2 * lk;
                float b0 = bias[col], b1 = bias[col + 1];
                float2 v0 = {acc[mt][nt][0] + b0, acc[mt][nt][1] + b1};
                float2 v1 = {acc[mt][nt][2] + b0, acc[mt][nt][3] + b1};
                *(float2*)(g_h + (size_t)row * OUTF + col) = v0;
                *(float2*)(g_h + (size_t)(row + 8) * OUTF + col) = v1;
            }
        }
    }
}

// ============================================================
// batchnorm stats + finalize
// ============================================================
__global__ void colreduce_kernel() {
    const int c = threadIdx.x;
    const int r0 = blockIdx.x * 256;
    float s = 0.f, s2 = 0.f;
    for (int r = r0; r < r0 + 256; ++r) {
        float v = g_h[(size_t)r * OUTF + c];
        s += v; s2 += v * v;
    }
    atomicAdd(&g_sum[c], s);
    atomicAdd(&g_sumsq[c], s2);
}
__global__ void finalize_bn_kernel(const float* __restrict__ gamma,
                                   const float* __restrict__ beta) {
    int c = threadIdx.x;
    float mu  = g_sum[c]   * (1.0f / NTOT);
    float var = g_sumsq[c] * (1.0f / NTOT) - mu * mu;
    float rs  = 1.0f / sqrtf(var + 1e-5f);
    float a   = gamma[c] * rs;
    g_a[c] = a;
    g_b2[c] = beta[c] - mu * a;
}

// ============================================================
// KNN coarse: 1-pass bf16-hi HMMA -> fp16 distances
// ============================================================
__global__ __launch_bounds__(256) void knn_coarse_kernel() {
    __shared__ __align__(16) char smbuf[2 * TILEB];
    __shared__ int s_rows[128];
    const uint32_t sA = smem_u32(smbuf);
    const uint32_t sB = sA + TILEB;

    const int tid = threadIdx.x, lane = tid & 31, wid = tid >> 5;
    const int wm = wid & 3, wn = wid >> 2;
    const int c = blockIdx.z;
    const int bm = blockIdx.y * 128;
    const int bn = blockIdx.x * 128;

    if (tid < 128) s_rows[tid] = c * Pc + g_fps[c * Sc + bm + tid];

    float acc[2][8][4];
#pragma unroll
    for (int i = 0; i < 2; ++i)
#pragma unroll
        for (int j = 0; j < 8; ++j)
#pragma unroll
            for (int l = 0; l < 4; ++l) acc[i][j][l] = 0.f;

    const int lr = tid >> 1, lh = tid & 1;
    const uint32_t soff = lr * STRB + lh * 16;
    const uint32_t lmoff = (lane & 15) * STRB + (lane >> 4) * 16;
    __syncthreads();
    const size_t arow = (size_t)s_rows[lr] * INF_;
    const size_t brow = (size_t)(c * Pc + bn + lr) * INF_;

    uint4 va = *(const uint4*)(g_fhi + arow + lh * 8);
    uint4 vb = *(const uint4*)(g_fhi + brow + lh * 8);

    for (int kc = 0; kc < 16; ++kc) {
        __syncthreads();
        *(uint4*)(smbuf + 0 * TILEB + soff) = va;
        *(uint4*)(smbuf + 1 * TILEB + soff) = vb;
        __syncthreads();
        if (kc + 1 < 16) {
            int k0 = (kc + 1) * 16;
            va = *(const uint4*)(g_fhi + arow + k0 + lh * 8);
            vb = *(const uint4*)(g_fhi + brow + k0 + lh * 8);
        }

        uint32_t a[2][4];
#pragma unroll
        for (int mt = 0; mt < 2; ++mt) {
            uint32_t base = (wm * 32 + mt * 16) * STRB + lmoff;
            ldsm4(a[mt][0], a[mt][1], a[mt][2], a[mt][3], sA + base);
        }
#pragma unroll
        for (int np2 = 0; np2 < 4; ++np2) {
            uint32_t base = (wn * 64 + np2 * 16) * STRB + lmoff;
            uint32_t h0, h1, h2, h3;
            ldsm4(h0, h1, h2, h3, sB + base);
            uint32_t b0[2] = {h0, h2}, b1[2] = {h1, h3};
#pragma unroll
            for (int mt = 0; mt < 2; ++mt) {
                mma16816(acc[mt][np2 * 2 + 0], a[mt], b0);
                mma16816(acc[mt][np2 * 2 + 1], a[mt], b1);
            }
        }
    }

#pragma unroll
    for (int mt = 0; mt < 2; ++mt) {
        int q = c * Sc + bm + wm * 32 + mt * 16 + (lane >> 2);
#pragma unroll
        for (int nt = 0; nt < 8; ++nt) {
            int col = bn + wn * 64 + nt * 8 + (lane & 3) * 2;
            float x0 = g_xnorm[c * Pc + col], x1 = g_xnorm[c * Pc + col + 1];
            float d0 = fmaxf(-2.f * acc[mt][nt][0] + x0, 0.f);
            float d1 = fmaxf(-2.f * acc[mt][nt][1] + x1, 0.f);
            float d2 = fmaxf(-2.f * acc[mt][nt][2] + x0, 0.f);
            float d3 = fmaxf(-2.f * acc[mt][nt][3] + x1, 0.f);
            *(__half2*)(g_dist16 + (size_t)q * Pc + col) = __floats2half2_rn(d0, d1);
            *(__half2*)(g_dist16 + (size_t)(q + 8) * Pc + col) = __floats2half2_rn(d2, d3);
        }
    }
}

// ============================================================
// select: coarse top-24 per query (packed u32 = dist16<<16 | idx)
// ============================================================
__global__ __launch_bounds__(256) void select_kernel() {
    const int q = blockIdx.x * 8 + (threadIdx.x >> 5);
    const int lane = threadIdx.x & 31;
    const uint32_t* row = (const uint32_t*)(g_dist16 + (size_t)q * Pc);

    uint32_t bd[NCAND];
#pragma unroll
    for (int j = 0; j < NCAND; ++j) bd[j] = 0xFFFFFFFFu;

#pragma unroll 1
    for (int it = 0; it < Pc / 64; ++it) {       // 64 iters, 2 cols per load
        int i = it * 32 + lane;
        uint32_t w = row[i];
        uint32_t c0 = (w << 16) | (uint32_t)(2 * i);
        uint32_t c1 = (w & 0xFFFF0000u) | (uint32_t)(2 * i + 1);
        if (c0 < bd[NCAND - 1]) {
            uint32_t cv = c0;
#pragma unroll
            for (int j = 0; j < NCAND; ++j) {
                uint32_t lo = umin(bd[j], cv), hi = umax(bd[j], cv);
                bd[j] = lo; cv = hi;
            }
        }
        if (c1 < bd[NCAND - 1]) {
            uint32_t cv = c1;
#pragma unroll
            for (int j = 0; j < NCAND; ++j) {
                uint32_t lo = umin(bd[j], cv), hi = umax(bd[j], cv);
                bd[j] = lo; cv = hi;
            }
        }
    }

    // warp merge: 24 sequential extractions of global min
#pragma unroll 1
    for (int r = 0; r < NCAND; ++r) {
        uint32_t v = bd[0];
#pragma unroll
        for (int off = 16; off > 0; off >>= 1)
            v = umin(v, __shfl_xor_sync(0xffffffffu, v, off));
        if (bd[0] == v) {      // unique winner (idx unique)
#pragma unroll
            for (int j = 0; j < NCAND - 1; ++j) bd[j] = bd[j + 1];
            bd[NCAND - 1] = 0xFFFFFFFFu;
        }
        if (lane == 0) g_cand[q * NCAND + r] = (int)(v & 0xFFFFu);
    }
}

// ============================================================
// rerank: exact fp32 distances for 24 candidates -> top-16
// ============================================================
__global__ __launch_bounds__(256) void rerank_kernel(const float* __restrict__ F) {
    const int q = blockIdx.x * 8 + (threadIdx.x >> 5);
    const int lane = threadIdx.x & 31;
    const int c = q >> 10;
    const int qg = c * Pc + g_fps[q];
    const float qn = g_xnorm[qg];

    float qv[8];
    {
        float4 v0 = *(const float4*)(F + (size_t)qg * INF_ + lane * 8);
        float4 v1 = *(const float4*)(F + (size_t)qg * INF_ + lane * 8 + 4);
        qv[0] = v0.x; qv[1] = v0.y; qv[2] = v0.z; qv[3] = v0.w;
        qv[4] = v1.x; qv[5] = v1.y; qv[6] = v1.z; qv[7] = v1.w;
    }

    float myd = 3.402823466e+38f;
    int   myi = 0x7fffffff;
#pragma unroll 1
    for (int k = 0; k < NCAND; ++k) {
        int cd = g_cand[q * NCAND + k];
        int xg = c * Pc + cd;
        const float* xr = F + (size_t)xg * INF_;
        float4 v0 = *(const float4*)(xr + lane * 8);
        float4 v1 = *(const float4*)(xr + lane * 8 + 4);
        float s = qv[0] * v0.x + qv[1] * v0.y + qv[2] * v0.z + qv[3] * v0.w
                + qv[4] * v1.x + qv[5] * v1.y + qv[6] * v1.z + qv[7] * v1.w;
#pragma unroll
        for (int off = 16; off > 0; off >>= 1) s += __shfl_xor_sync(0xffffffffu, s, off);
        float d = qn - 2.f * s + g_xnorm[xg];
        if (lane == k) { myd = d; myi = cd; }
    }

#pragma unroll 1
    for (int r = 0; r < Kc; ++r) {
        float v = myd; int idx = myi;
#pragma unroll
        for (int off = 16; off > 0; off >>= 1) {
            float ov = __shfl_xor_sync(0xffffffffu, v, off);
            int   oi = __shfl_xor_sync(0xffffffffu, idx, off);
            if (ov < v || (ov == v && oi < idx)) { v = ov; idx = oi; }
        }
        if (myi == idx) { myd = 3.402823466e+38f; myi = 0x7fffffff; }
        if (lane == 0) g_knn[q * Kc + r] = c * Pc + idx;
    }
}

// ============================================================
// max-pool + BN affine + relu
// ============================================================
__global__ __launch_bounds__(128) void pool_kernel(float* __restrict__ out_nf) {
    const int q = blockIdx.x, tid = threadIdx.x;
    __shared__ int rows[Kc];
    if (tid < Kc) rows[tid] = g_knn[q * Kc + tid];
    __syncthreads();

    float mx[4], mn[4];
#pragma unroll
    for (int j = 0; j < 4; ++j) { mx[j] = -1e30f; mn[j] = 1e30f; }
#pragma unroll 1
    for (int k = 0; k < Kc; ++k) {
        const float* hr = g_h + (size_t)rows[k] * OUTF;
#pragma unroll
        for (int j = 0; j < 4; ++j) {
            float v = hr[tid + j * 128];
            mx[j] = fmaxf(mx[j], v);
            mn[j] = fminf(mn[j], v);
        }
    }
#pragma unroll
    for (int j = 0; j < 4; ++j) {
        int c = tid + j * 128;
        float a = g_a[c];
        float m = (a >= 0.f) ? mx[j] : mn[j];
        out_nf[(size_t)q * OUTF + c] = fmaxf(a * m + g_b2[c], 0.f);
    }
}

// ============================================================
// launch
// ============================================================
extern "C" void kernel_launch(void* const* d_in, const int* in_sizes, int n_in,
                              void* d_out, int out_size) {
    const float* features  = (const float*)d_in[0];
    const float* positions = (const float*)d_in[1];
    const float* W     = (const float*)d_in[3];
    const float* bias  = (const float*)d_in[4];
    const float* gamma = (const float*)d_in[5];
    const float* beta  = (const float*)d_in[6];

    float* out = (float*)d_out;
    const long long nf_elems  = (long long)QTOT * OUTF;
    const long long pos_elems = (long long)QTOT * 3;
    int write_pos   = (out_size >= nf_elems + pos_elems) ? 1 : 0;
    int write_batch = (out_size >= nf_elems + pos_elems + QTOT) ? 1 : 0;
    float* out_pos   = out + nf_elems;
    float* out_batch = out + nf_elems + pos_elems;

    zero_sums_kernel<<<1, OUTF>>>();
    prep_w_kernel<<<OUTF, INF_>>>(W);
    fat_kernel<<<FAT_GRID, 256>>>(features, positions, bias,
                                  out_pos, out_batch, write_pos, write_batch);
    colreduce_kernel<<<NTOT / 256, OUTF>>>();
    finalize_bn_kernel<<<1, OUTF>>>(gamma, beta);
    knn_coarse_kernel<<<dim3(Pc / 128, Sc / 128, Bc), 256>>>();
    select_kernel<<<QTOT / 8, 256>>>();
    rerank_kernel<<<QTOT / 8, 256>>>(features);
    pool_kernel<<<QTOT, 128>>>(out);
}